// round 5
// baseline (speedup 1.0000x reference)
#include <cuda_runtime.h>
#include <math.h>

// ---------------------------------------------------------------------------
// ExtractorMLP edge attention:
//   P = emb @ [W1_top | W1_bot]            (precompute, [N,1024])
//   h1 = relu(P[col][0:512] + P[row][512:1024] + b1)
//   h2 = relu(h1 @ W2 + b2);  att = sigmoid(h2 @ W3 + b3)
// edge_index is int32 (JAX x64-disabled truncates the declared int64).
// ---------------------------------------------------------------------------

#define HDIM      128
#define H4        512        // 4H
#define PW        1024       // width of P (two 512 halves)
#define MAXN      100000

// Scratch: P matrix (~410 MB). __device__ global per harness rules.
__device__ float g_P[(size_t)MAXN * PW];

// ============================ Kernel 1: P = emb @ W1cat =====================
// Tile: 64 nodes x 128 cols, 256 threads, per-thread 8 nodes x 4 cols.
#define BM1 64
#define BN1 128
#define KK1 32

__global__ __launch_bounds__(256) void gemm_p_kernel(
    const float* __restrict__ emb, const float* __restrict__ W1, int N)
{
    __shared__ float embS[KK1][BM1 + 1];   // [k][node]
    __shared__ float wS[KK1][BN1];         // [k][col]

    const int bm   = blockIdx.x * BM1;
    const int bn   = blockIdx.y * BN1;
    const int tid  = threadIdx.x;
    const int lane = tid & 31;
    const int warp = tid >> 5;             // 0..7, owns 8 nodes

    float acc[8][4];
    #pragma unroll
    for (int i = 0; i < 8; i++)
        { acc[i][0]=0.f; acc[i][1]=0.f; acc[i][2]=0.f; acc[i][3]=0.f; }

    for (int kc = 0; kc < HDIM; kc += KK1) {
        // stage emb tile (transposed): 64 nodes x 32 k
        #pragma unroll
        for (int i = 0; i < 8; i++) {
            int id = tid + i * 256;
            int m  = id >> 5;              // node within tile
            int k  = id & 31;
            int node = bm + m;
            float v = 0.f;
            if (node < N) v = emb[(size_t)node * HDIM + kc + k];
            embS[k][m] = v;
        }
        // stage W1cat tile: 32 k x 128 cols (cols bn..bn+127 of the 1024)
        #pragma unroll
        for (int i = 0; i < 16; i++) {
            int id = tid + i * 256;
            int j  = id & 127;
            int k  = id >> 7;
            int jj = bn + j;
            int kg = kc + k;
            float w = (jj < H4) ? W1[(size_t)kg * H4 + jj]
                                : W1[(size_t)(kg + HDIM) * H4 + (jj - H4)];
            wS[k][j] = w;
        }
        __syncthreads();

        #pragma unroll 8
        for (int kk = 0; kk < KK1; kk++) {
            float4 w4 = *(const float4*)&wS[kk][lane * 4];
            #pragma unroll
            for (int i = 0; i < 8; i++) {
                float e = embS[kk][warp * 8 + i];   // warp broadcast
                acc[i][0] += e * w4.x;
                acc[i][1] += e * w4.y;
                acc[i][2] += e * w4.z;
                acc[i][3] += e * w4.w;
            }
        }
        __syncthreads();
    }

    #pragma unroll
    for (int i = 0; i < 8; i++) {
        int node = bm + warp * 8 + i;
        if (node < N) {
            float4 v = make_float4(acc[i][0], acc[i][1], acc[i][2], acc[i][3]);
            *(float4*)&g_P[(size_t)node * PW + bn + lane * 4] = v;
        }
    }
}

// ===================== Kernel 2: per-edge layers 1..3 + sigmoid =============
// Tile: 128 edges x 128 output cols per block, 256 threads.
// Per thread: 16 edges (warp-owned) x 4 cols (lane-owned). K-chunks of 32.
#define EB  128
#define KK2 32

__global__ __launch_bounds__(256) void edge_mlp_kernel(
    const int* __restrict__ ei,           // [2, E] int32
    const float* __restrict__ b1,         // [512]
    const float* __restrict__ W2,         // [512,128]
    const float* __restrict__ b2,         // [128]
    const float* __restrict__ W3,         // [128]
    const float* __restrict__ b3,         // [1]
    float* __restrict__ out, int E, int N)
{
    __shared__ float h1S[KK2][EB + 1];    // [k][edge]
    __shared__ float w2S[KK2][HDIM];      // [k][col]
    __shared__ int   colS[EB], rowS[EB];
    __shared__ float outS[EB];

    const int tid  = threadIdx.x;
    const int lane = tid & 31;
    const int warp = tid >> 5;            // 0..7
    const int eb   = blockIdx.x * EB;

    if (tid < EB) {
        int e = eb + tid;
        int c = 0, r = 0;
        if (e < E) {
            c = ei[e];
            r = ei[(size_t)E + e];
            // safety: never fault, even on bad indices (shows up as rel_err)
            if ((unsigned)c >= (unsigned)N) c = 0;
            if ((unsigned)r >= (unsigned)N) r = 0;
        }
        colS[tid] = c;
        rowS[tid] = r;
    }
    __syncthreads();

    float acc[16][4];
    #pragma unroll
    for (int i = 0; i < 16; i++)
        { acc[i][0]=0.f; acc[i][1]=0.f; acc[i][2]=0.f; acc[i][3]=0.f; }

    for (int kc = 0; kc < H4; kc += KK2) {
        // build h1 chunk: warp w handles edges p*8+w, lanes cover 32 k (coalesced)
        float bv = b1[kc + lane];
        #pragma unroll
        for (int p = 0; p < 16; p++) {
            int e = p * 8 + warp;
            int c = colS[e], r = rowS[e];
            float v = g_P[(size_t)c * PW + kc + lane]
                    + g_P[(size_t)r * PW + H4 + kc + lane] + bv;
            h1S[lane][e] = fmaxf(v, 0.f);
        }
        // stage W2 chunk: 32 k x 128 cols
        #pragma unroll
        for (int i = 0; i < 16; i++) {
            int id = tid + i * 256;
            int j  = id & 127;
            int k  = id >> 7;
            w2S[k][j] = W2[(size_t)(kc + k) * HDIM + j];
        }
        __syncthreads();

        #pragma unroll 8
        for (int kk = 0; kk < KK2; kk++) {
            float4 w4 = *(const float4*)&w2S[kk][lane * 4];
            #pragma unroll
            for (int i = 0; i < 16; i++) {
                float h = h1S[kk][warp * 16 + i];   // warp broadcast
                acc[i][0] += h * w4.x;
                acc[i][1] += h * w4.y;
                acc[i][2] += h * w4.z;
                acc[i][3] += h * w4.w;
            }
        }
        __syncthreads();
    }

    // Epilogue: relu(acc + b2) . W3, warp-reduce over the 32 lane col-groups.
    float4 w3v = *(const float4*)&W3[lane * 4];
    float4 b2v = *(const float4*)&b2[lane * 4];
    #pragma unroll
    for (int i = 0; i < 16; i++) {
        float t = fmaxf(acc[i][0] + b2v.x, 0.f) * w3v.x
                + fmaxf(acc[i][1] + b2v.y, 0.f) * w3v.y
                + fmaxf(acc[i][2] + b2v.z, 0.f) * w3v.z
                + fmaxf(acc[i][3] + b2v.w, 0.f) * w3v.w;
        #pragma unroll
        for (int o = 16; o > 0; o >>= 1)
            t += __shfl_down_sync(0xffffffffu, t, o);
        if (lane == 0) outS[warp * 16 + i] = t;
    }
    __syncthreads();

    if (tid < EB) {
        int e = eb + tid;
        if (e < E) {
            float x = outS[tid] + b3[0];
            out[e] = 1.f / (1.f + expf(-x));
        }
    }
}

// ============================== Launch ======================================
extern "C" void kernel_launch(void* const* d_in, const int* in_sizes, int n_in,
                              void* d_out, int out_size)
{
    const float* emb = (const float*)d_in[0];
    const int*   ei  = (const int*)d_in[1];     // int32 (JAX default x64=off)
    const float* W1  = (const float*)d_in[2];
    const float* b1  = (const float*)d_in[3];
    const float* W2  = (const float*)d_in[4];
    const float* b2  = (const float*)d_in[5];
    const float* W3  = (const float*)d_in[6];
    const float* b3  = (const float*)d_in[7];
    float*       out = (float*)d_out;

    const int N = in_sizes[0] / HDIM;      // 100000
    const int E = in_sizes[1] / 2;         // 1000000

    dim3 g1((N + BM1 - 1) / BM1, PW / BN1);
    gemm_p_kernel<<<g1, 256>>>(emb, W1, N);

    dim3 g2((E + EB - 1) / EB);
    edge_mlp_kernel<<<g2, 256>>>(ei, b1, W2, b2, W3, b3, out, E, N);
}

// round 9
// speedup vs baseline: 2.1849x; 2.1849x over previous
#include <cuda_runtime.h>
#include <math.h>
#include <stdint.h>

// ---------------------------------------------------------------------------
// ExtractorMLP edge attention. Baseline-sm_103-compatible tensor path:
//   P = emb @ [W1_top | W1_bot]                  (fp32 FFMA GEMM, [N,1024])
//   h1 = relu(P[col][0:512] + P[row][512:] + b1) (fp32, built per K-chunk)
//   h2 = h1 @ W2  via mma.sync m16n8k8 tf32 (tensor pipe, fp32 accum)
//   out = sigmoid(relu(h2+b2) @ W3 + b3)         (fp32 epilogue)
// NOTE: tcgen05/TMEM is *_a-only; harness PTX target is plain sm_103, so
// mma.sync is the fastest legal tensor path here.
// ---------------------------------------------------------------------------

#define HDIM 128
#define H4   512
#define PW   1024
#define MAXN 100000
#define EB   128          // edges per block
#define KC   32           // K-chunk
#define NCHUNK (H4 / KC)  // 16

__device__ float g_P[(size_t)MAXN * PW];
__device__ float g_W2tf[H4 * HDIM];   // W2 pre-rounded to tf32

__device__ __forceinline__ float to_tf32(float x) {
    float r;
    asm("cvt.rna.tf32.f32 %0, %1;" : "=f"(r) : "f"(x));
    return r;
}

__device__ __forceinline__ void mma_tf32(float& c0, float& c1, float& c2, float& c3,
                                         uint32_t a0, uint32_t a1, uint32_t a2, uint32_t a3,
                                         uint32_t b0, uint32_t b1) {
    asm volatile(
        "mma.sync.aligned.m16n8k8.row.col.f32.tf32.tf32.f32 "
        "{%0,%1,%2,%3}, {%4,%5,%6,%7}, {%8,%9}, {%0,%1,%2,%3};"
        : "+f"(c0), "+f"(c1), "+f"(c2), "+f"(c3)
        : "r"(a0), "r"(a1), "r"(a2), "r"(a3), "r"(b0), "r"(b1));
}

// =============== Prep: W2 -> tf32-rounded copy ==============================
__global__ void prep_w2_kernel(const float* __restrict__ W2) {
    int id = blockIdx.x * 256 + threadIdx.x;
    if (id < H4 * HDIM) g_W2tf[id] = to_tf32(W2[id]);
}

// ============================ Kernel 1: P = emb @ W1cat =====================
#define BM1 64
#define BN1 128
#define KK1 32

__global__ __launch_bounds__(256) void gemm_p_kernel(
    const float* __restrict__ emb, const float* __restrict__ W1, int N)
{
    __shared__ float embS[KK1][BM1 + 1];
    __shared__ float wS[KK1][BN1];

    const int bm = blockIdx.x * BM1, bn = blockIdx.y * BN1;
    const int tid = threadIdx.x, lane = tid & 31, warp = tid >> 5;

    float acc[8][4];
    #pragma unroll
    for (int i = 0; i < 8; i++)
        { acc[i][0]=0.f; acc[i][1]=0.f; acc[i][2]=0.f; acc[i][3]=0.f; }

    for (int kc = 0; kc < HDIM; kc += KK1) {
        #pragma unroll
        for (int i = 0; i < 8; i++) {
            int id = tid + i * 256;
            int m = id >> 5, k = id & 31;
            int node = bm + m;
            embS[k][m] = (node < N) ? emb[(size_t)node * HDIM + kc + k] : 0.f;
        }
        #pragma unroll
        for (int i = 0; i < 16; i++) {
            int id = tid + i * 256;
            int j = id & 127, k = id >> 7;
            int jj = bn + j, kg = kc + k;
            wS[k][j] = (jj < H4) ? W1[(size_t)kg * H4 + jj]
                                 : W1[(size_t)(kg + HDIM) * H4 + (jj - H4)];
        }
        __syncthreads();
        #pragma unroll 8
        for (int kk = 0; kk < KK1; kk++) {
            float4 w4 = *(const float4*)&wS[kk][lane * 4];
            #pragma unroll
            for (int i = 0; i < 8; i++) {
                float e = embS[kk][warp * 8 + i];
                acc[i][0] += e * w4.x; acc[i][1] += e * w4.y;
                acc[i][2] += e * w4.z; acc[i][3] += e * w4.w;
            }
        }
        __syncthreads();
    }
    #pragma unroll
    for (int i = 0; i < 8; i++) {
        int node = bm + warp * 8 + i;
        if (node < N) {
            float4 v = make_float4(acc[i][0], acc[i][1], acc[i][2], acc[i][3]);
            *(float4*)&g_P[(size_t)node * PW + bn + lane * 4] = v;
        }
    }
}

// ================== Kernel 2: mma.sync tf32 edge MLP ========================
// 256 threads = 8 warps in 4(M) x 2(N) grid; warp tile 32 edges x 64 cols.
__global__ __launch_bounds__(256) void edge_mlp_mma_kernel(
    const int* __restrict__ ei,
    const float* __restrict__ b1,
    const float* __restrict__ b2,
    const float* __restrict__ W3,
    const float* __restrict__ b3,
    float* __restrict__ out, int E, int N)
{
    __shared__ float h1S[KC][EB + 4];     // [k][edge], tf32-rounded
    __shared__ float w2S[KC][HDIM + 4];   // [k][col],  tf32-rounded
    __shared__ float partS[2][EB];        // per-warpN row partials
    __shared__ int   colS[EB], rowS[EB];
    __shared__ float b2S[HDIM], w3S[HDIM];

    const int tid   = threadIdx.x;
    const int lane  = tid & 31;
    const int wid   = tid >> 5;
    const int warpM = wid & 3;            // 0..3 -> edge band of 32
    const int warpN = wid >> 2;           // 0..1 -> col band of 64
    const int quad  = lane >> 2;          // 0..7
    const int tq    = lane & 3;           // 0..3
    const int eb    = blockIdx.x * EB;

    if (tid < EB) {
        int e = eb + tid, c = 0, r = 0;
        if (e < E) {
            c = ei[e]; r = ei[(size_t)E + e];
            if ((unsigned)c >= (unsigned)N) c = 0;
            if ((unsigned)r >= (unsigned)N) r = 0;
        }
        colS[tid] = c; rowS[tid] = r;
    }
    if (tid < HDIM) { b2S[tid] = b2[tid]; w3S[tid] = W3[tid]; }
    __syncthreads();

    float acc[2][8][4];
    #pragma unroll
    for (int mf = 0; mf < 2; mf++)
        #pragma unroll
        for (int nf = 0; nf < 8; nf++)
            { acc[mf][nf][0]=0.f; acc[mf][nf][1]=0.f;
              acc[mf][nf][2]=0.f; acc[mf][nf][3]=0.f; }

    for (int ch = 0; ch < NCHUNK; ch++) {
        const int kc = ch * KC;

        // ---- stage h1 chunk: 128 edges x 32 k (1024 float4 jobs) ----
        #pragma unroll
        for (int it = 0; it < 4; it++) {
            int id = tid + it * 256;
            int e  = id & 127;
            int j  = id >> 7;                 // 0..7, k-quad
            int c  = colS[e], r = rowS[e];
            float4 a4 = *(const float4*)&g_P[(size_t)c * PW + kc + j * 4];
            float4 c4 = *(const float4*)&g_P[(size_t)r * PW + H4 + kc + j * 4];
            float4 bv = *(const float4*)&b1[kc + j * 4];
            h1S[j * 4 + 0][e] = to_tf32(fmaxf(a4.x + c4.x + bv.x, 0.f));
            h1S[j * 4 + 1][e] = to_tf32(fmaxf(a4.y + c4.y + bv.y, 0.f));
            h1S[j * 4 + 2][e] = to_tf32(fmaxf(a4.z + c4.z + bv.z, 0.f));
            h1S[j * 4 + 3][e] = to_tf32(fmaxf(a4.w + c4.w + bv.w, 0.f));
        }
        // ---- stage W2 chunk: 32 k x 128 cols (1024 float4) ----
        #pragma unroll
        for (int it = 0; it < 4; it++) {
            int id = tid + it * 256;
            int n4 = id & 31;                 // col quad
            int k  = id >> 5;                 // 0..31
            float4 w = *(const float4*)&g_W2tf[(size_t)(kc + k) * HDIM + n4 * 4];
            *(float4*)&w2S[k][n4 * 4] = w;
        }
        __syncthreads();

        // ---- 4 k8-steps of m16n8k8 tf32 MMA ----
        #pragma unroll
        for (int ks = 0; ks < 4; ks++) {
            const int k0 = ks * 8 + tq;
            uint32_t a[2][4];
            #pragma unroll
            for (int mf = 0; mf < 2; mf++) {
                int m = warpM * 32 + mf * 16 + quad;
                a[mf][0] = __float_as_uint(h1S[k0    ][m]);
                a[mf][1] = __float_as_uint(h1S[k0    ][m + 8]);
                a[mf][2] = __float_as_uint(h1S[k0 + 4][m]);
                a[mf][3] = __float_as_uint(h1S[k0 + 4][m + 8]);
            }
            uint32_t b[8][2];
            #pragma unroll
            for (int nf = 0; nf < 8; nf++) {
                int n = warpN * 64 + nf * 8 + quad;
                b[nf][0] = __float_as_uint(w2S[k0    ][n]);
                b[nf][1] = __float_as_uint(w2S[k0 + 4][n]);
            }
            #pragma unroll
            for (int mf = 0; mf < 2; mf++)
                #pragma unroll
                for (int nf = 0; nf < 8; nf++)
                    mma_tf32(acc[mf][nf][0], acc[mf][nf][1],
                             acc[mf][nf][2], acc[mf][nf][3],
                             a[mf][0], a[mf][1], a[mf][2], a[mf][3],
                             b[nf][0], b[nf][1]);
        }
        __syncthreads();
    }

    // ---- Epilogue: relu(h2+b2).W3, reduce, sigmoid ----
    #pragma unroll
    for (int mf = 0; mf < 2; mf++) {
        #pragma unroll
        for (int h = 0; h < 2; h++) {
            float s = 0.f;
            #pragma unroll
            for (int nf = 0; nf < 8; nf++) {
                int col = warpN * 64 + nf * 8 + tq * 2;
                float v0 = acc[mf][nf][h * 2 + 0];
                float v1 = acc[mf][nf][h * 2 + 1];
                s += fmaxf(v0 + b2S[col], 0.f) * w3S[col]
                   + fmaxf(v1 + b2S[col + 1], 0.f) * w3S[col + 1];
            }
            s += __shfl_xor_sync(0xffffffffu, s, 1);
            s += __shfl_xor_sync(0xffffffffu, s, 2);
            if (tq == 0)
                partS[warpN][warpM * 32 + mf * 16 + h * 8 + quad] = s;
        }
    }
    __syncthreads();

    if (tid < EB) {
        int e = eb + tid;
        if (e < E) {
            float x = partS[0][tid] + partS[1][tid] + b3[0];
            out[e] = 1.f / (1.f + expf(-x));
        }
    }
}

// ============================== Launch ======================================
extern "C" void kernel_launch(void* const* d_in, const int* in_sizes, int n_in,
                              void* d_out, int out_size)
{
    const float* emb = (const float*)d_in[0];
    const int*   ei  = (const int*)d_in[1];
    const float* W1  = (const float*)d_in[2];
    const float* b1  = (const float*)d_in[3];
    const float* W2  = (const float*)d_in[4];
    const float* b2  = (const float*)d_in[5];
    const float* W3  = (const float*)d_in[6];
    const float* b3  = (const float*)d_in[7];
    float*       out = (float*)d_out;

    const int N = in_sizes[0] / HDIM;
    const int E = in_sizes[1] / 2;

    prep_w2_kernel<<<(H4 * HDIM + 255) / 256, 256>>>(W2);

    dim3 g1((N + BM1 - 1) / BM1, PW / BN1);
    gemm_p_kernel<<<g1, 256>>>(emb, W1, N);

    dim3 g2((E + EB - 1) / EB);
    edge_mlp_mma_kernel<<<g2, 256>>>(ei, b1, b2, W3, b3, out, E, N);
}

// round 11
// speedup vs baseline: 3.2720x; 1.4976x over previous
#include <cuda_runtime.h>
#include <math.h>
#include <stdint.h>

// ---------------------------------------------------------------------------
// ExtractorMLP edge attention. All GEMMs on tensor pipe via mma.sync tf32:
//   P = emb @ [W1_top | W1_bot]        (tf32 mma, [N,1024] fp32 out)
//   h1 = relu(P[col][0:512] + P[row][512:] + b1)   (fp32, per K-chunk)
//   h2 = h1 @ W2                       (tf32 mma, cp.async depth-3 pipeline)
//   out = sigmoid(relu(h2+b2) @ W3 + b3)
// ---------------------------------------------------------------------------

#define HDIM 128
#define H4   512
#define PW   1024
#define MAXN 100000
#define EB   128
#define KC   32
#define NCHUNK (H4 / KC)   // 16

__device__ float g_P[(size_t)MAXN * PW];
__device__ float g_W2tf[H4 * HDIM];     // W2 pre-rounded to tf32

__device__ __forceinline__ float to_tf32(float x) {
    float r;
    asm("cvt.rna.tf32.f32 %0, %1;" : "=f"(r) : "f"(x));
    return r;
}

__device__ __forceinline__ void mma_tf32(float& c0, float& c1, float& c2, float& c3,
                                         uint32_t a0, uint32_t a1, uint32_t a2, uint32_t a3,
                                         uint32_t b0, uint32_t b1) {
    asm volatile(
        "mma.sync.aligned.m16n8k8.row.col.f32.tf32.tf32.f32 "
        "{%0,%1,%2,%3}, {%4,%5,%6,%7}, {%8,%9}, {%0,%1,%2,%3};"
        : "+f"(c0), "+f"(c1), "+f"(c2), "+f"(c3)
        : "r"(a0), "r"(a1), "r"(a2), "r"(a3), "r"(b0), "r"(b1));
}

__device__ __forceinline__ uint32_t smem_u32(const void* p) {
    uint32_t a;
    asm("{ .reg .u64 t; cvta.to.shared.u64 t, %1; cvt.u32.u64 %0, t; }"
        : "=r"(a) : "l"(p));
    return a;
}
__device__ __forceinline__ void cp16(uint32_t dst, const void* src) {
    asm volatile("cp.async.ca.shared.global [%0], [%1], 16;" :: "r"(dst), "l"(src));
}
#define CP_COMMIT() asm volatile("cp.async.commit_group;" ::: "memory")
#define CP_WAIT1()  asm volatile("cp.async.wait_group 1;" ::: "memory")

// =============== Prep: W2 -> tf32-rounded copy ==============================
__global__ void prep_w2_kernel(const float* __restrict__ W2) {
    int id = blockIdx.x * 256 + threadIdx.x;
    if (id < H4 * HDIM) g_W2tf[id] = to_tf32(W2[id]);
}

// ================= Kernel 1: P = emb @ W1cat (tf32 mma) =====================
// 128 nodes x 128 cols per block; 8 warps 4(M)x2(N); K=128 in 4 chunks of 32.
#define BM1 128
#define BN1 128

__global__ __launch_bounds__(256) void gemm_p_mma_kernel(
    const float* __restrict__ emb, const float* __restrict__ W1, int N)
{
    __shared__ __align__(16) float eS[KC][BM1 + 4];
    __shared__ __align__(16) float wS[KC][BN1 + 4];

    const int tid   = threadIdx.x;
    const int lane  = tid & 31;
    const int wid   = tid >> 5;
    const int warpM = wid & 3;
    const int warpN = wid >> 2;
    const int quad  = lane >> 2;
    const int tq    = lane & 3;
    const int bm    = blockIdx.x * BM1;
    const int bn    = blockIdx.y * BN1;

    const int half = (bn >= H4) ? 1 : 0;
    const float* W1b = W1 + (size_t)(half ? HDIM : 0) * H4 + (bn - (half ? H4 : 0));

    float acc[2][8][4];
    #pragma unroll
    for (int mf = 0; mf < 2; mf++)
        #pragma unroll
        for (int nf = 0; nf < 8; nf++)
            { acc[mf][nf][0]=0.f; acc[mf][nf][1]=0.f;
              acc[mf][nf][2]=0.f; acc[mf][nf][3]=0.f; }

    for (int ch = 0; ch < 4; ch++) {
        const int kc = ch * KC;
        // stage emb tile (coalesced: 4 nodes x 128B per warp-op)
        #pragma unroll
        for (int it = 0; it < 4; it++) {
            int id = tid + it * 256;
            int m = id >> 3, j = id & 7;
            int node = bm + m;
            float4 v = make_float4(0.f, 0.f, 0.f, 0.f);
            if (node < N) v = *(const float4*)&emb[(size_t)node * HDIM + kc + j * 4];
            eS[j * 4 + 0][m] = to_tf32(v.x);
            eS[j * 4 + 1][m] = to_tf32(v.y);
            eS[j * 4 + 2][m] = to_tf32(v.z);
            eS[j * 4 + 3][m] = to_tf32(v.w);
        }
        // stage W1 tile
        #pragma unroll
        for (int it = 0; it < 4; it++) {
            int id = tid + it * 256;
            int k = id >> 5, s = id & 31;
            float4 w = *(const float4*)&W1b[(size_t)(kc + k) * H4 + s * 4];
            wS[k][s * 4 + 0] = to_tf32(w.x);
            wS[k][s * 4 + 1] = to_tf32(w.y);
            wS[k][s * 4 + 2] = to_tf32(w.z);
            wS[k][s * 4 + 3] = to_tf32(w.w);
        }
        __syncthreads();

        #pragma unroll
        for (int ks = 0; ks < 4; ks++) {
            const int k0 = ks * 8 + tq;
            uint32_t a[2][4];
            #pragma unroll
            for (int mf = 0; mf < 2; mf++) {
                int m = warpM * 32 + mf * 16 + quad;
                a[mf][0] = __float_as_uint(eS[k0    ][m]);
                a[mf][1] = __float_as_uint(eS[k0    ][m + 8]);
                a[mf][2] = __float_as_uint(eS[k0 + 4][m]);
                a[mf][3] = __float_as_uint(eS[k0 + 4][m + 8]);
            }
            uint32_t b[8][2];
            #pragma unroll
            for (int nf = 0; nf < 8; nf++) {
                int n = warpN * 64 + nf * 8 + quad;
                b[nf][0] = __float_as_uint(wS[k0    ][n]);
                b[nf][1] = __float_as_uint(wS[k0 + 4][n]);
            }
            #pragma unroll
            for (int mf = 0; mf < 2; mf++)
                #pragma unroll
                for (int nf = 0; nf < 8; nf++)
                    mma_tf32(acc[mf][nf][0], acc[mf][nf][1],
                             acc[mf][nf][2], acc[mf][nf][3],
                             a[mf][0], a[mf][1], a[mf][2], a[mf][3],
                             b[nf][0], b[nf][1]);
        }
        __syncthreads();
    }

    // store P
    #pragma unroll
    for (int mf = 0; mf < 2; mf++) {
        #pragma unroll
        for (int h = 0; h < 2; h++) {
            int node = bm + warpM * 32 + mf * 16 + h * 8 + quad;
            if (node < N) {
                #pragma unroll
                for (int nf = 0; nf < 8; nf++) {
                    int col = bn + warpN * 64 + nf * 8 + tq * 2;
                    float2 v = make_float2(acc[mf][nf][h * 2], acc[mf][nf][h * 2 + 1]);
                    *(float2*)&g_P[(size_t)node * PW + col] = v;
                }
            }
        }
    }
}

// =========== Kernel 2: cp.async-pipelined tf32 edge MLP =====================
// Dynamic smem ring (depth 3): raw col-half, raw row-half, W2 chunk. h1 single.
#define RAWC_OFF 0           // 3 * 4096 floats ([e][j] cells, 128B per edge)
#define RAWR_OFF 12288
#define W2_OFF   24576       // 3 * 4224 (rows of 132)
#define H1_OFF   37248       // 4224
#define DYN_FLOATS 41472
#define DYN_BYTES (DYN_FLOATS * 4)

__global__ __launch_bounds__(256) void edge_mlp_mma_kernel(
    const int* __restrict__ ei,
    const float* __restrict__ b1,
    const float* __restrict__ b2,
    const float* __restrict__ W3,
    const float* __restrict__ b3,
    float* __restrict__ out, int E, int N)
{
    extern __shared__ __align__(16) float dyn[];
    __shared__ int   colS[EB], rowS[EB];
    __shared__ __align__(16) float b1S[H4];
    __shared__ float b2S[HDIM], w3S[HDIM];
    __shared__ float partS[2][EB];

    const int tid   = threadIdx.x;
    const int lane  = tid & 31;
    const int wid   = tid >> 5;
    const int warpM = wid & 3;
    const int warpN = wid >> 2;
    const int quad  = lane >> 2;
    const int tq    = lane & 3;
    const int eb    = blockIdx.x * EB;

    const uint32_t sbase = smem_u32(dyn);

    if (tid < EB) {
        int e = eb + tid, c = 0, r = 0;
        if (e < E) {
            c = ei[e]; r = ei[(size_t)E + e];
            if ((unsigned)c >= (unsigned)N) c = 0;
            if ((unsigned)r >= (unsigned)N) r = 0;
        }
        colS[tid] = c; rowS[tid] = r;
    }
    b1S[tid]       = b1[tid];
    b1S[tid + 256] = b1[tid + 256];
    if (tid < HDIM) { b2S[tid] = b2[tid]; w3S[tid] = W3[tid]; }
    __syncthreads();

    // ---- async issue for chunk ch into ring slot ch%3 ----
    auto issue = [&](int ch) {
        const int b  = ch % 3;
        const int kc = ch * KC;
        #pragma unroll
        for (int it = 0; it < 4; it++) {
            int id = tid + it * 256;
            int e = id >> 3, j = id & 7;
            int c = colS[e], r = rowS[e];
            uint32_t dC = sbase + (uint32_t)(RAWC_OFF + b * 4096 + e * 32 + j * 4) * 4u;
            uint32_t dR = sbase + (uint32_t)(RAWR_OFF + b * 4096 + e * 32 + j * 4) * 4u;
            cp16(dC, &g_P[(size_t)c * PW + kc + j * 4]);
            cp16(dR, &g_P[(size_t)r * PW + H4 + kc + j * 4]);
        }
        #pragma unroll
        for (int it = 0; it < 4; it++) {
            int id = tid + it * 256;
            int k = id >> 5, s = id & 31;
            uint32_t dW = sbase + (uint32_t)(W2_OFF + b * 4224 + k * 132 + s * 4) * 4u;
            cp16(dW, &g_W2tf[(size_t)(kc + k) * HDIM + s * 4]);
        }
    };

    issue(0); CP_COMMIT();
    issue(1); CP_COMMIT();

    float acc[2][8][4];
    #pragma unroll
    for (int mf = 0; mf < 2; mf++)
        #pragma unroll
        for (int nf = 0; nf < 8; nf++)
            { acc[mf][nf][0]=0.f; acc[mf][nf][1]=0.f;
              acc[mf][nf][2]=0.f; acc[mf][nf][3]=0.f; }

    for (int ch = 0; ch < NCHUNK; ch++) {
        const int b  = ch % 3;
        const int kc = ch * KC;

        CP_WAIT1();
        __syncthreads();       // chunk-ch data visible; prev iter fully done

        // compute h1 chunk from raw buffers (conflict-free LDS.128)
        #pragma unroll
        for (int it = 0; it < 4; it++) {
            int id = tid + it * 256;
            int e = id >> 3, j = id & 7;
            float4 pc = *(const float4*)&dyn[RAWC_OFF + b * 4096 + e * 32 + j * 4];
            float4 pr = *(const float4*)&dyn[RAWR_OFF + b * 4096 + e * 32 + j * 4];
            float4 bv = *(const float4*)&b1S[kc + j * 4];
            dyn[H1_OFF + (j * 4 + 0) * 132 + e] = to_tf32(fmaxf(pc.x + pr.x + bv.x, 0.f));
            dyn[H1_OFF + (j * 4 + 1) * 132 + e] = to_tf32(fmaxf(pc.y + pr.y + bv.y, 0.f));
            dyn[H1_OFF + (j * 4 + 2) * 132 + e] = to_tf32(fmaxf(pc.z + pr.z + bv.z, 0.f));
            dyn[H1_OFF + (j * 4 + 3) * 132 + e] = to_tf32(fmaxf(pc.w + pr.w + bv.w, 0.f));
        }
        if (ch + 2 < NCHUNK) issue(ch + 2);
        CP_COMMIT();           // one group per iteration (possibly empty)
        __syncthreads();       // h1S ready

        const float* w2b = &dyn[W2_OFF + b * 4224];
        const float* h1  = &dyn[H1_OFF];
        #pragma unroll
        for (int ks = 0; ks < 4; ks++) {
            const int k0 = ks * 8 + tq;
            uint32_t a[2][4];
            #pragma unroll
            for (int mf = 0; mf < 2; mf++) {
                int m = warpM * 32 + mf * 16 + quad;
                a[mf][0] = __float_as_uint(h1[k0 * 132 + m]);
                a[mf][1] = __float_as_uint(h1[k0 * 132 + m + 8]);
                a[mf][2] = __float_as_uint(h1[(k0 + 4) * 132 + m]);
                a[mf][3] = __float_as_uint(h1[(k0 + 4) * 132 + m + 8]);
            }
            uint32_t bfr[8][2];
            #pragma unroll
            for (int nf = 0; nf < 8; nf++) {
                int n = warpN * 64 + nf * 8 + quad;
                bfr[nf][0] = __float_as_uint(w2b[k0 * 132 + n]);
                bfr[nf][1] = __float_as_uint(w2b[(k0 + 4) * 132 + n]);
            }
            #pragma unroll
            for (int mf = 0; mf < 2; mf++)
                #pragma unroll
                for (int nf = 0; nf < 8; nf++)
                    mma_tf32(acc[mf][nf][0], acc[mf][nf][1],
                             acc[mf][nf][2], acc[mf][nf][3],
                             a[mf][0], a[mf][1], a[mf][2], a[mf][3],
                             bfr[nf][0], bfr[nf][1]);
        }
    }

    // ---- Epilogue: relu(h2+b2).W3, reduce, sigmoid ----
    #pragma unroll
    for (int mf = 0; mf < 2; mf++) {
        #pragma unroll
        for (int h = 0; h < 2; h++) {
            float s = 0.f;
            #pragma unroll
            for (int nf = 0; nf < 8; nf++) {
                int col = warpN * 64 + nf * 8 + tq * 2;
                float v0 = acc[mf][nf][h * 2 + 0];
                float v1 = acc[mf][nf][h * 2 + 1];
                s += fmaxf(v0 + b2S[col], 0.f) * w3S[col]
                   + fmaxf(v1 + b2S[col + 1], 0.f) * w3S[col + 1];
            }
            s += __shfl_xor_sync(0xffffffffu, s, 1);
            s += __shfl_xor_sync(0xffffffffu, s, 2);
            if (tq == 0)
                partS[warpN][warpM * 32 + mf * 16 + h * 8 + quad] = s;
        }
    }
    __syncthreads();

    if (tid < EB) {
        int e = eb + tid;
        if (e < E) {
            float x = partS[0][tid] + partS[1][tid] + b3[0];
            out[e] = 1.f / (1.f + expf(-x));
        }
    }
}

// ============================== Launch ======================================
extern "C" void kernel_launch(void* const* d_in, const int* in_sizes, int n_in,
                              void* d_out, int out_size)
{
    const float* emb = (const float*)d_in[0];
    const int*   ei  = (const int*)d_in[1];
    const float* W1  = (const float*)d_in[2];
    const float* b1  = (const float*)d_in[3];
    const float* W2  = (const float*)d_in[4];
    const float* b2  = (const float*)d_in[5];
    const float* W3  = (const float*)d_in[6];
    const float* b3  = (const float*)d_in[7];
    float*       out = (float*)d_out;

    const int N = in_sizes[0] / HDIM;
    const int E = in_sizes[1] / 2;

    static int init_done = 0;
    if (!init_done) {
        cudaFuncSetAttribute(edge_mlp_mma_kernel,
                             cudaFuncAttributeMaxDynamicSharedMemorySize, DYN_BYTES);
        init_done = 1;
    }

    prep_w2_kernel<<<(H4 * HDIM + 255) / 256, 256>>>(W2);

    dim3 g1((N + BM1 - 1) / BM1, PW / BN1);
    gemm_p_mma_kernel<<<g1, 256>>>(emb, W1, N);

    dim3 g2((E + EB - 1) / EB);
    edge_mlp_mma_kernel<<<g2, 256, DYN_BYTES>>>(ei, b1, b2, W3, b3, out, E, N);
}